// round 10
// baseline (speedup 1.0000x reference)
#include <cuda_runtime.h>
#include <cstdint>

// ---------------------------------------------------------------------------
// QuantizerEncoder: persistent warp-specialized pipeline.
//   consumers (8 warps): tf32 m16n8k8 HMMA screening + warp-level top-2
//   producers (4 warps): convert next tile (LDG->tf32->STS) + reduce/store
//                        previous tile's top-2 + flag ambiguous entries
// Flagged entries recomputed exactly in fp32 by refine_kernel.
// ---------------------------------------------------------------------------

typedef unsigned long long ULL;

__device__ float g_A[262144];             // tf32-hi, m16n8k8 A-frag layout
__device__ float g_MT[4 * 128 * 256];     // fp32 M^T [m][d][k] (refine)
__device__ int   g_cnt[4];                // flagged counts per m
__device__ int   g_list[4 * 65536];       // flagged pixel lists per m

#define GAP_TH 0.05f
#define NSM 148
#define NUNITS 2048

static __device__ __forceinline__ uint32_t f2tf32(float v) {
    uint32_t u;
    asm("cvt.rna.tf32.f32 %0, %1;" : "=r"(u) : "f"(v));
    return u;
}

static __device__ __forceinline__ void mma8(float* d, float4 a, float2 b) {
    asm volatile(
        "mma.sync.aligned.m16n8k8.row.col.f32.tf32.tf32.f32 "
        "{%0,%1,%2,%3}, {%4,%5,%6,%7}, {%8,%9}, {%0,%1,%2,%3};"
        : "+f"(d[0]), "+f"(d[1]), "+f"(d[2]), "+f"(d[3])
        : "r"(__float_as_uint(a.x)), "r"(__float_as_uint(a.y)),
          "r"(__float_as_uint(a.z)), "r"(__float_as_uint(a.w)),
          "r"(__float_as_uint(b.x)), "r"(__float_as_uint(b.y)));
}

static __device__ __forceinline__ unsigned mono(float f) {
    unsigned u = __float_as_uint(f);
    return (u & 0x80000000u) ? ~u : (u | 0x80000000u);
}
static __device__ __forceinline__ float imono(unsigned u) {
    return (u & 0x80000000u) ? __uint_as_float(u & 0x7fffffffu)
                             : __uint_as_float(~u);
}

// ---------------- fused setup: keys (smem) -> Mmat -> g_A/g_MT --------------
__global__ __launch_bounds__(256, 1)
void setup_kernel(const float* __restrict__ cb, const float* __restrict__ wk,
                  const float* __restrict__ wq) {
    extern __shared__ float sm[];
    float* skeys = sm + 16512;   // [8 k][128 c]
    float* scb   = sm + 17536;   // [8 k][128 d]
    const int m = blockIdx.y, kch = blockIdx.x, t = threadIdx.x;

    const float4* wk4 = (const float4*)(wk + (size_t)m * 16384);
#pragma unroll
    for (int i = 0; i < 16; i++) {
        int j = i * 256 + t, c = j >> 5, d4 = j & 31;
        float4 v = __ldg(wk4 + j);
        sm[(4 * d4 + 0) * 129 + c] = v.x;
        sm[(4 * d4 + 1) * 129 + c] = v.y;
        sm[(4 * d4 + 2) * 129 + c] = v.z;
        sm[(4 * d4 + 3) * 129 + c] = v.w;
    }
    ((float4*)scb)[t] = __ldg((const float4*)(cb + ((size_t)m * 256 + kch * 8) * 128) + t);
    __syncthreads();
    {
        int c = t & 127, b = t >> 7;
        float s0 = 0.f, s1 = 0.f, s2 = 0.f, s3 = 0.f;
#pragma unroll 8
        for (int d = 0; d < 128; d++) {
            float w = sm[d * 129 + c];
            s0 += scb[(b + 0) * 128 + d] * w;
            s1 += scb[(b + 2) * 128 + d] * w;
            s2 += scb[(b + 4) * 128 + d] * w;
            s3 += scb[(b + 6) * 128 + d] * w;
        }
        skeys[(b + 0) * 128 + c] = s0;
        skeys[(b + 2) * 128 + c] = s1;
        skeys[(b + 4) * 128 + c] = s2;
        skeys[(b + 6) * 128 + c] = s3;
    }
    __syncthreads();

    const float4* wq4 = (const float4*)(wq + (size_t)m * 16384);
#pragma unroll
    for (int i = 0; i < 16; i++) ((float4*)sm)[i * 256 + t] = __ldg(wq4 + i * 256 + t);
    __syncthreads();
    {
        int d = t & 127, b = t >> 7;
        float v0 = 0.f, v1 = 0.f, v2 = 0.f, v3 = 0.f;
#pragma unroll 8
        for (int c = 0; c < 128; c++) {
            float w = sm[c * 128 + d];
            v0 += w * skeys[(b + 0) * 128 + c];
            v1 += w * skeys[(b + 2) * 128 + c];
            v2 += w * skeys[(b + 4) * 128 + c];
            v3 += w * skeys[(b + 6) * 128 + c];
        }
        float vals[4] = {v0, v1, v2, v3};
#pragma unroll
        for (int q = 0; q < 4; q++) {
            int kl = b + 2 * q;
            int k = kch * 8 + kl;
            float val = vals[q];
            g_MT[((size_t)m * 128 + d) * 256 + k] = val;

            uint32_t hib = f2tf32(val);
            int half_ = k >> 7, w = (k & 127) >> 4, r = k & 15;
            int ks = d >> 3, dc = d & 7;
            int ln, fi;
            if (r < 8) { ln = r * 4 + (dc & 3); fi = (dc >= 4) ? 2 : 0; }
            else       { ln = (r - 8) * 4 + (dc & 3); fi = (dc >= 4) ? 3 : 1; }
            size_t base = (size_t)(((m * 2 + half_) * 8 + w) * 16 + ks) * 128 + ln * 4 + fi;
            g_A[base] = __uint_as_float(hib);
        }
    }
    if (blockIdx.x == 0 && blockIdx.y == 0 && t < 4) g_cnt[t] = 0;
}

// ---------------- stage 1: persistent warp-specialized score ----------------
// grid = 148 CTAs, 384 threads (8 consumer warps + 4 producer warps).
// unit u = cta + i*148, u in [0,2048): m = u>>9, tile = u&511.
// smem floats: B0 [0,17408) B1 [17408,34816)
//   gk0 @34816 (4096f) gk1 @38912  gs0 @43008 (2048f) gs1 @45056; tot 47104 f.
__global__ __launch_bounds__(384, 1)
void score_kernel(const float* __restrict__ latent, float* __restrict__ out) {
    extern __shared__ float sb[];
    const int t = threadIdx.x, lane = t & 31, wid = t >> 5;
    const int cta = blockIdx.x;
    const int my_units = (NUNITS - cta + NSM - 1) / NSM;
    const bool is_cons = (t < 256);
    const int pt = t - 256;  // producer-local tid (0..127)

    // ---- prologue: producers convert unit u0 into B0 ----
    if (!is_cons) {
        int u = cta;
        int m = u >> 9, tile = u & 511;
        const float* xb = latent +
            ((size_t)((tile >> 5) * 512 + m * 128)) * 4096 + ((tile & 31) << 7);
#pragma unroll
        for (int it0 = 0; it0 < 32; it0 += 8) {
            float4 v[8];
#pragma unroll
            for (int j = 0; j < 8; j++) {
                int g = (it0 + j) * 128 + pt;
                v[j] = __ldg((const float4*)(xb + (size_t)(g >> 5) * 4096) + (g & 31));
            }
#pragma unroll
            for (int j = 0; j < 8; j++) {
                int g = (it0 + j) * 128 + pt;
                float4 tf;
                tf.x = __uint_as_float(f2tf32(v[j].x));
                tf.y = __uint_as_float(f2tf32(v[j].y));
                tf.z = __uint_as_float(f2tf32(v[j].z));
                tf.w = __uint_as_float(f2tf32(v[j].w));
                *(float4*)(sb + (g >> 5) * 136 + (g & 31) * 4) = tf;
            }
        }
    }
    __syncthreads();

    for (int i = 0; i <= my_units; i++) {
        if (is_cons) {
            if (i < my_units) {
                const int u = cta + i * NSM;
                const int m = u >> 9;
                const float* Bb = sb + (i & 1) * 17408;
                ULL* gk = (ULL*)(sb + 34816 + (i & 1) * 4096);
                unsigned* gs = (unsigned*)(sb + 43008 + (i & 1) * 2048);

                for (int half_ = 0; half_ < 2; half_++) {
                    float acc[16][4];
#pragma unroll
                    for (int j = 0; j < 16; j++)
#pragma unroll
                        for (int c = 0; c < 4; c++) acc[j][c] = 0.f;

                    const float4* pA = ((const float4*)g_A) +
                                       (size_t)((m * 2 + half_) * 8 + wid) * 512;
#pragma unroll
                    for (int kg = 0; kg < 2; kg++) {
                        float4 afr[8];
#pragma unroll
                        for (int ki = 0; ki < 8; ki++)
                            afr[ki] = __ldg(pA + (kg * 8 + ki) * 32 + lane);
#pragma unroll
                        for (int ki = 0; ki < 8; ki++) {
                            int ks = kg * 8 + ki;
                            const float* bbase =
                                Bb + (ks * 8 + (lane & 3)) * 136 + (lane >> 2);
#pragma unroll
                            for (int j = 0; j < 16; j++) {
                                float2 b = make_float2(bbase[j * 8], bbase[544 + j * 8]);
                                mma8(acc[j], afr[ki], b);
                            }
                        }
                    }

                    // warp-level top-2 over this warp's 16 codes
                    int r0 = half_ * 128 + wid * 16 + (lane >> 2);
#pragma unroll
                    for (int j = 0; j < 16; j++) {
#pragma unroll
                        for (int cc = 0; cc < 2; cc++) {
                            unsigned u0 = mono(acc[j][cc]);
                            unsigned u1 = mono(acc[j][2 + cc]);
                            ULL k0 = ((ULL)u0 << 32) | (unsigned)(255 - r0);
                            ULL k1 = ((ULL)u1 << 32) | (unsigned)(255 - (r0 + 8));
                            ULL key = (k0 > k1) ? k0 : k1;
                            unsigned us = (u0 < u1) ? u0 : u1;
#pragma unroll
                            for (int o = 4; o <= 16; o <<= 1) {
                                ULL ok = __shfl_xor_sync(0xffffffffu, key, o);
                                unsigned os = __shfl_xor_sync(0xffffffffu, us, o);
                                unsigned loser_b = (unsigned)(((key < ok) ? key : ok) >> 32);
                                unsigned win_s = (key > ok) ? us : os;
                                us = (loser_b > win_s) ? loser_b : win_s;
                                key = (key > ok) ? key : ok;
                            }
                            if (lane < 4) {
                                int px = j * 8 + lane * 2 + cc;
                                gk[(half_ * 8 + wid) * 128 + px] = key;
                                gs[(half_ * 8 + wid) * 128 + px] = us;
                            }
                        }
                    }
                }
            }
        } else {
            // ---- producers: convert unit i+1 into B[(i+1)&1] ----
            if (i + 1 < my_units) {
                const int u = cta + (i + 1) * NSM;
                const int m = u >> 9, tile = u & 511;
                const float* xb = latent +
                    ((size_t)((tile >> 5) * 512 + m * 128)) * 4096 + ((tile & 31) << 7);
                float* Bd = sb + ((i + 1) & 1) * 17408;
#pragma unroll
                for (int it0 = 0; it0 < 32; it0 += 8) {
                    float4 v[8];
#pragma unroll
                    for (int j = 0; j < 8; j++) {
                        int g = (it0 + j) * 128 + pt;
                        v[j] = __ldg((const float4*)(xb + (size_t)(g >> 5) * 4096) + (g & 31));
                    }
#pragma unroll
                    for (int j = 0; j < 8; j++) {
                        int g = (it0 + j) * 128 + pt;
                        float4 tf;
                        tf.x = __uint_as_float(f2tf32(v[j].x));
                        tf.y = __uint_as_float(f2tf32(v[j].y));
                        tf.z = __uint_as_float(f2tf32(v[j].z));
                        tf.w = __uint_as_float(f2tf32(v[j].w));
                        *(float4*)(Bd + (g >> 5) * 136 + (g & 31) * 4) = tf;
                    }
                }
            }
            // ---- producers: reduce+store unit i-1 from gk[(i-1)&1] ----
            if (i >= 1) {
                const int up = cta + (i - 1) * NSM;
                const int mp = up >> 9, tilep = up & 511;
                const int pixbase = (tilep >> 5) * 4096 + ((tilep & 31) << 7);
                const ULL* gk = (const ULL*)(sb + 34816 + ((i - 1) & 1) * 4096);
                const unsigned* gs = (const unsigned*)(sb + 43008 + ((i - 1) & 1) * 2048);

                int px = pt;
                ULL k1 = gk[px];
                int g1 = 0;
                unsigned u2 = 0;
#pragma unroll
                for (int g = 1; g < 16; g++) {
                    ULL kb = gk[g * 128 + px];
                    if (kb > k1) {
                        unsigned pb = (unsigned)(k1 >> 32);
                        if (pb > u2) u2 = pb;
                        k1 = kb; g1 = g;
                    } else {
                        unsigned pb = (unsigned)(kb >> 32);
                        if (pb > u2) u2 = pb;
                    }
                }
                unsigned sw = gs[g1 * 128 + px];
                if (sw > u2) u2 = sw;
                float f1 = imono((unsigned)(k1 >> 32));
                float f2 = imono(u2);
                int code = 255 - (int)(k1 & 0xFF);
                int pix = pixbase + px;
                out[pix * 4 + mp] = (float)code;
                if (f1 - f2 < GAP_TH) {
                    int pos = atomicAdd(&g_cnt[mp], 1);
                    g_list[mp * 65536 + pos] = pix;
                }
            }
        }
        __syncthreads();
    }
}

// ---------------- stage 2: batched exact fp32 refine (flattened) ------------
__global__ __launch_bounds__(256, 2)
void refine_kernel(const float* __restrict__ latent, float* __restrict__ out) {
    __shared__ float xs[128 * 32];     // [d][e]
    __shared__ ULL redk[32 * 64];      // [e][c4]
    __shared__ int spix[32];

    const int t = threadIdx.x;
    const int c0 = g_cnt[0], c1 = g_cnt[1], c2 = g_cnt[2], c3 = g_cnt[3];
    const int nb0 = (c0 + 31) >> 5, nb1 = (c1 + 31) >> 5;
    const int nb2 = (c2 + 31) >> 5, nb3 = (c3 + 31) >> 5;
    const int tot = nb0 + nb1 + nb2 + nb3;

    for (int jb = blockIdx.x; jb < tot; jb += gridDim.x) {
        int m, lb, cnt;
        if (jb < nb0)                  { m = 0; lb = jb; cnt = c0; }
        else if (jb < nb0 + nb1)       { m = 1; lb = jb - nb0; cnt = c1; }
        else if (jb < nb0 + nb1 + nb2) { m = 2; lb = jb - nb0 - nb1; cnt = c2; }
        else                           { m = 3; lb = jb - nb0 - nb1 - nb2; cnt = c3; }
        int ne = cnt - lb * 32;
        if (ne > 32) ne = 32;

        if (t < 32)
            spix[t] = g_list[m * 65536 + lb * 32 + ((t < ne) ? t : 0)];
        __syncthreads();

        {
            int e = t & 31, d0 = (t >> 5) * 16;
            int pp = spix[e];
            const float* xp = latent +
                ((size_t)((pp >> 12) * 512 + m * 128 + d0)) * 4096 + (pp & 4095);
            float v[16];
#pragma unroll
            for (int i = 0; i < 16; i++) v[i] = __ldg(xp + (size_t)i * 4096);
#pragma unroll
            for (int i = 0; i < 16; i++) xs[(d0 + i) * 32 + e] = v[i];
        }
        __syncthreads();

        const int c4 = t & 63, eg = t >> 6;
        float acc[4][8];
#pragma unroll
        for (int c = 0; c < 4; c++)
#pragma unroll
            for (int k = 0; k < 8; k++) acc[c][k] = 0.f;

        const float4* MT = (const float4*)(g_MT + (size_t)m * 32768);
#pragma unroll 4
        for (int d = 0; d < 128; d++) {
            float4 mv = __ldg(MT + d * 64 + c4);
            float4 xa = *(const float4*)(xs + d * 32 + eg * 8);
            float4 xc = *(const float4*)(xs + d * 32 + eg * 8 + 4);
            float xv[8] = {xa.x, xa.y, xa.z, xa.w, xc.x, xc.y, xc.z, xc.w};
#pragma unroll
            for (int k = 0; k < 8; k++) {
                acc[0][k] += mv.x * xv[k];
                acc[1][k] += mv.y * xv[k];
                acc[2][k] += mv.z * xv[k];
                acc[3][k] += mv.w * xv[k];
            }
        }

#pragma unroll
        for (int k = 0; k < 8; k++) {
            ULL key = 0;
#pragma unroll
            for (int c = 0; c < 4; c++) {
                int code = c4 * 4 + c;
                ULL kk = ((ULL)mono(acc[c][k]) << 32) | (unsigned)(255 - code);
                if (kk > key) key = kk;
            }
            redk[(eg * 8 + k) * 64 + c4] = key;
        }
        __syncthreads();

        {
            int e2 = t >> 3, ch = t & 7;
            ULL best = redk[e2 * 64 + ch * 8];
#pragma unroll
            for (int q = 1; q < 8; q++) {
                ULL o = redk[e2 * 64 + ch * 8 + q];
                if (o > best) best = o;
            }
#pragma unroll
            for (int o = 1; o < 8; o <<= 1) {
                ULL ob = __shfl_xor_sync(0xffffffffu, best, o);
                if (ob > best) best = ob;
            }
            if (ch == 0 && e2 < ne)
                out[spix[e2] * 4 + m] = (float)(255 - (int)(best & 0xFF));
        }
        __syncthreads();
    }
}

extern "C" void kernel_launch(void* const* d_in, const int* in_sizes, int n_in,
                              void* d_out, int out_size) {
    const float* latent = (const float*)d_in[0];
    const float* cb     = (const float*)d_in[1];
    const float* wq     = (const float*)d_in[2];
    const float* wk     = (const float*)d_in[3];

    cudaFuncSetAttribute(setup_kernel, cudaFuncAttributeMaxDynamicSharedMemorySize, 74240);
    cudaFuncSetAttribute(score_kernel, cudaFuncAttributeMaxDynamicSharedMemorySize, 188416);

    setup_kernel<<<dim3(32, 4), 256, 74240>>>(cb, wk, wq);
    score_kernel<<<NSM, 384, 188416>>>(latent, (float*)d_out);
    refine_kernel<<<512, 256>>>(latent, (float*)d_out);
}